// round 2
// baseline (speedup 1.0000x reference)
#include <cuda_runtime.h>
#include <math.h>
#include <stdint.h>

#define NMAX 262144

// ---------------- scratch (device globals; no allocation allowed) ------------
struct ScratchT {
    float    h1[4 * NMAX];   // conv1 accum: h0, h1, cnt, pad
    float    h2[4 * NMAX];   // conv2 accum: 4 channels
    double   stats[12];      // sum1[2], sumsq1[2], sum2[4], sumsq2[4]
    unsigned done1, done2;   // last-block counters
};
__device__ ScratchT g;
__device__ float    g_h1e[2 * NMAX];   // elu(mean(h1)) packed float2
__device__ float    g_inv[NMAX];       // 1 / max(cnt,1)
__device__ float    g_scale1[2], g_shift1[2];
__device__ float    g_scale2[4], g_shift2[4];
__device__ unsigned g_poolmax[64], g_poolmin[64];  // pre-BN pooled, ordered-uint
__device__ int      g_idx64;

// ordered-uint encoding: unsigned max/min == float max/min
__device__ __forceinline__ unsigned fenc(float f) {
    unsigned u = __float_as_uint(f);
    return (u & 0x80000000u) ? ~u : (u | 0x80000000u);
}
__device__ __forceinline__ float fdec(unsigned u) {
    return (u & 0x80000000u) ? __uint_as_float(u & 0x7FFFFFFFu)
                             : __uint_as_float(~u);
}
#define ENC_NEG_INF 0x007FFFFFu
#define ENC_MAX     0xFFFFFFFFu

// ---------------- prelude: init pool slots + sniff index dtype ---------------
__global__ void k_prelude(const unsigned* __restrict__ eidx_words, int E) {
    int t = threadIdx.x;
    if (t < 64) { g_poolmax[t] = ENC_NEG_INF; g_poolmin[t] = ENC_MAX; }
    if (t == 0) {
        // int64 little-endian with values < 2^31 => every odd word is 0.
        int is64 = 1;
        int nchk = (E < 64) ? E : 64;
        for (int i = 0; i < nchk; i++)
            if (eidx_words[2 * i + 1] != 0u) { is64 = 0; break; }
        g_idx64 = is64;
    }
}

// ---------------- basis + tiny matmul helpers --------------------------------
// conv1: out2 = (sum_b w_b W1[b][0][:]) , W layout [8][2]
__device__ __forceinline__ void combo1(float v0, float v1, float v2,
                                       const float* __restrict__ sW,
                                       float& a0, float& a1) {
    float l0 = floorf(v0), l1 = floorf(v1), l2 = floorf(v2);
    float f0 = v0 - l0, f1 = v1 - l1, f2 = v2 - l2;
    if (l0 == 0.f && l1 == 0.f && l2 == 0.f) {     // pseudo in [0,1): always
        float g0 = 1.f - f0, g1 = 1.f - f1, g2 = 1.f - f2;
#pragma unroll
        for (int o = 0; o < 2; o++) {
            float t00 = g0 * sW[0 + o] + f0 * sW[2 + o];
            float t01 = g0 * sW[4 + o] + f0 * sW[6 + o];
            float t10 = g0 * sW[8 + o] + f0 * sW[10 + o];
            float t11 = g0 * sW[12 + o] + f0 * sW[14 + o];
            float r = (g1 * t00 + f1 * t01) * g2 + (g1 * t10 + f1 * t11) * f2;
            if (o == 0) a0 = r; else a1 = r;
        }
    } else {                                        // generic clamp path
        float gr0 = 1.f - f0, gr1 = 1.f - f1, gr2 = 1.f - f2;
        int i00 = min(max((int)l0, 0), 1), i01 = min(max((int)l0 + 1, 0), 1);
        int i10 = min(max((int)l1, 0), 1), i11 = min(max((int)l1 + 1, 0), 1);
        int i20 = min(max((int)l2, 0), 1), i21 = min(max((int)l2 + 1, 0), 1);
        a0 = 0.f; a1 = 0.f;
#pragma unroll
        for (int b = 0; b < 8; b++) {
            float w = ((b & 1) ? f0 : gr0) * ((b & 2) ? f1 : gr1) * ((b & 4) ? f2 : gr2);
            int idx = ((b & 1) ? i01 : i00) + 2 * ((b & 2) ? i11 : i10) + 4 * ((b & 4) ? i21 : i20);
            a0 = fmaf(w, sW[2 * idx + 0], a0);
            a1 = fmaf(w, sW[2 * idx + 1], a1);
        }
    }
}

// conv2: acc4 += sum_b w_b (h0 W[b][0][:] + h1 W[b][1][:]), W layout [8][2][4]
__device__ __forceinline__ void combo2(float v0, float v1, float v2,
                                       float h0, float h1,
                                       const float* __restrict__ sW,
                                       float* acc) {
    float l0 = floorf(v0), l1 = floorf(v1), l2 = floorf(v2);
    float f0 = v0 - l0, f1 = v1 - l1, f2 = v2 - l2;
    if (l0 == 0.f && l1 == 0.f && l2 == 0.f) {
        float g0 = 1.f - f0, g1 = 1.f - f1, g2 = 1.f - f2;
#pragma unroll
        for (int o = 0; o < 4; o++) {
            float q0 = h0 * sW[0 + o]  + h1 * sW[4 + o];
            float q1 = h0 * sW[8 + o]  + h1 * sW[12 + o];
            float q2 = h0 * sW[16 + o] + h1 * sW[20 + o];
            float q3 = h0 * sW[24 + o] + h1 * sW[28 + o];
            float q4 = h0 * sW[32 + o] + h1 * sW[36 + o];
            float q5 = h0 * sW[40 + o] + h1 * sW[44 + o];
            float q6 = h0 * sW[48 + o] + h1 * sW[52 + o];
            float q7 = h0 * sW[56 + o] + h1 * sW[60 + o];
            float u0 = g1 * (g0 * q0 + f0 * q1) + f1 * (g0 * q2 + f0 * q3);
            float u1 = g1 * (g0 * q4 + f0 * q5) + f1 * (g0 * q6 + f0 * q7);
            acc[o] = g2 * u0 + f2 * u1;
        }
    } else {
        float gr0 = 1.f - f0, gr1 = 1.f - f1, gr2 = 1.f - f2;
        int i00 = min(max((int)l0, 0), 1), i01 = min(max((int)l0 + 1, 0), 1);
        int i10 = min(max((int)l1, 0), 1), i11 = min(max((int)l1 + 1, 0), 1);
        int i20 = min(max((int)l2, 0), 1), i21 = min(max((int)l2 + 1, 0), 1);
#pragma unroll
        for (int o = 0; o < 4; o++) acc[o] = 0.f;
#pragma unroll
        for (int b = 0; b < 8; b++) {
            float w = ((b & 1) ? f0 : gr0) * ((b & 2) ? f1 : gr1) * ((b & 4) ? f2 : gr2);
            int idx = ((b & 1) ? i01 : i00) + 2 * ((b & 2) ? i11 : i10) + 4 * ((b & 4) ? i21 : i20);
            const float* Wb = &sW[8 * idx];
#pragma unroll
            for (int o = 0; o < 4; o++)
                acc[o] = fmaf(w, fmaf(h0, Wb[o], h1 * Wb[4 + o]), acc[o]);
        }
    }
}

// ---------------- vectorized edge loads: 4 edges per thread ------------------
__device__ __forceinline__ void load4_idx(const void* eidx, int grp, int E, int is64,
                                          int* src, int* dst) {
    if (is64) {
        const longlong2* p = (const longlong2*)eidx;
        size_t off = (size_t)(E >> 1);
        longlong2 s0 = __ldg(&p[2 * grp]),       s1 = __ldg(&p[2 * grp + 1]);
        longlong2 d0 = __ldg(&p[off + 2 * grp]), d1 = __ldg(&p[off + 2 * grp + 1]);
        src[0] = (int)s0.x; src[1] = (int)s0.y; src[2] = (int)s1.x; src[3] = (int)s1.y;
        dst[0] = (int)d0.x; dst[1] = (int)d0.y; dst[2] = (int)d1.x; dst[3] = (int)d1.y;
    } else {
        const int4* p = (const int4*)eidx;
        int4 s = __ldg(&p[grp]), d = __ldg(&p[(E >> 2) + grp]);
        src[0] = s.x; src[1] = s.y; src[2] = s.z; src[3] = s.w;
        dst[0] = d.x; dst[1] = d.y; dst[2] = d.z; dst[3] = d.w;
    }
}
__device__ __forceinline__ void load4_attr(const float* attr, int grp, float* f) {
    const float4* a4 = (const float4*)attr;
    float4 A = __ldg(&a4[3 * grp]), B = __ldg(&a4[3 * grp + 1]), C = __ldg(&a4[3 * grp + 2]);
    f[0]=A.x; f[1]=A.y; f[2]=A.z; f[3]=A.w; f[4]=B.x;  f[5]=B.y;
    f[6]=B.z; f[7]=B.w; f[8]=C.x; f[9]=C.y; f[10]=C.z; f[11]=C.w;
}

// ---------------- conv1: x[N,1] x W1 -> red.v4 (h0,h1,cnt,0) -----------------
__global__ void __launch_bounds__(256) k_conv1(
        const float* __restrict__ x, const void* __restrict__ eidx,
        const float* __restrict__ attr, const float* __restrict__ W1, int E) {
    __shared__ float sW[16];
    __shared__ int   sI64;
    int t = threadIdx.x;
    if (t < 16) sW[t] = W1[t];
    if (t == 0) sI64 = g_idx64;
    __syncthreads();

    int grp  = blockIdx.x * 256 + t;
    int base = grp * 4;
    if (base >= E) return;

    if (base + 3 < E && (E & 3) == 0) {
        int src[4], dst[4];
        float f[12];
        load4_idx(eidx, grp, E, sI64, src, dst);
        load4_attr(attr, grp, f);
        float xs[4];
#pragma unroll
        for (int j = 0; j < 4; j++) xs[j] = __ldg(&x[src[j]]);
#pragma unroll
        for (int j = 0; j < 4; j++) {
            float a0, a1;
            combo1(f[3 * j], f[3 * j + 1], f[3 * j + 2], sW, a0, a1);
            a0 *= xs[j]; a1 *= xs[j];
            asm volatile("red.global.add.v4.f32 [%0], {%1, %2, %3, %4};"
                         :: "l"(&g.h1[4 * dst[j]]), "f"(a0), "f"(a1), "f"(1.0f), "f"(0.0f)
                         : "memory");
        }
    } else {  // tail / odd-E fallback: scalar loads
        for (int e = base; e < E && e < base + 4; e++) {
            int src, dst;
            if (sI64) {
                const long long* p = (const long long*)eidx;
                src = (int)__ldg(&p[e]); dst = (int)__ldg(&p[(size_t)E + e]);
            } else {
                const int* p = (const int*)eidx;
                src = __ldg(&p[e]); dst = __ldg(&p[E + e]);
            }
            float a0, a1;
            combo1(__ldg(&attr[3*e]), __ldg(&attr[3*e+1]), __ldg(&attr[3*e+2]), sW, a0, a1);
            float xs = __ldg(&x[src]);
            a0 *= xs; a1 *= xs;
            asm volatile("red.global.add.v4.f32 [%0], {%1, %2, %3, %4};"
                         :: "l"(&g.h1[4 * dst]), "f"(a0), "f"(a1), "f"(1.0f), "f"(0.0f)
                         : "memory");
        }
    }
}

// ---------------- finish1: mean -> ELU -> store, BN1 stats + params ----------
__global__ void __launch_bounds__(256) k_finish1(
        const float* __restrict__ gamma1, const float* __restrict__ beta1, int N) {
    int t = threadIdx.x;
    int n = blockIdx.x * 256 + t;
    float a = 0.f, b = 0.f;
    if (n < N) {
        float4 h  = *(const float4*)&g.h1[4 * n];
        float inv = 1.0f / fmaxf(h.z, 1.0f);
        g_inv[n] = inv;
        a = h.x * inv; b = h.y * inv;
        a = (a > 0.f) ? a : expm1f(a);
        b = (b > 0.f) ? b : expm1f(b);
        *(float2*)&g_h1e[2 * n] = make_float2(a, b);
    }
    float s0 = a, s1 = b, s2 = a * a, s3 = b * b;
#pragma unroll
    for (int o = 16; o; o >>= 1) {
        s0 += __shfl_down_sync(~0u, s0, o);
        s1 += __shfl_down_sync(~0u, s1, o);
        s2 += __shfl_down_sync(~0u, s2, o);
        s3 += __shfl_down_sync(~0u, s3, o);
    }
    if ((t & 31) == 0) {
        atomicAdd(&g.stats[0], (double)s0);
        atomicAdd(&g.stats[1], (double)s1);
        atomicAdd(&g.stats[2], (double)s2);
        atomicAdd(&g.stats[3], (double)s3);
    }
    __shared__ int last;
    __syncthreads();
    if (t == 0) {
        __threadfence();
        last = (atomicAdd(&g.done1, 1u) == gridDim.x - 1);
    }
    __syncthreads();
    if (last && t < 2) {
        __threadfence();
        double invN = 1.0 / (double)N;
        double mu   = g.stats[t] * invN;
        double var  = g.stats[2 + t] * invN - mu * mu;
        float  sc   = (float)((double)gamma1[t] / sqrt(var + 1e-5));
        g_scale1[t] = sc;
        g_shift1[t] = beta1[t] - (float)mu * sc;
    }
}

// ---------------- conv2: BN1(h1e)[N,2] x W2 -> red.v4 [N,4] ------------------
__global__ void __launch_bounds__(256) k_conv2(
        const void* __restrict__ eidx, const float* __restrict__ attr,
        const float* __restrict__ W2, int E) {
    __shared__ float sW[64];
    __shared__ float sSc[2], sSh[2];
    __shared__ int   sI64;
    int t = threadIdx.x;
    if (t < 64) sW[t] = W2[t];
    if (t < 2)  { sSc[t] = g_scale1[t]; sSh[t] = g_shift1[t]; }
    if (t == 0) sI64 = g_idx64;
    __syncthreads();

    int grp  = blockIdx.x * 256 + t;
    int base = grp * 4;
    if (base >= E) return;

    if (base + 3 < E && (E & 3) == 0) {
        int src[4], dst[4];
        float f[12];
        load4_idx(eidx, grp, E, sI64, src, dst);
        load4_attr(attr, grp, f);
        float2 h[4];
#pragma unroll
        for (int j = 0; j < 4; j++) h[j] = *(const float2*)&g_h1e[2 * src[j]];
#pragma unroll
        for (int j = 0; j < 4; j++) {
            float h0 = fmaf(h[j].x, sSc[0], sSh[0]);
            float h1 = fmaf(h[j].y, sSc[1], sSh[1]);
            float acc[4];
            combo2(f[3 * j], f[3 * j + 1], f[3 * j + 2], h0, h1, sW, acc);
            asm volatile("red.global.add.v4.f32 [%0], {%1, %2, %3, %4};"
                         :: "l"(&g.h2[4 * dst[j]]), "f"(acc[0]), "f"(acc[1]), "f"(acc[2]), "f"(acc[3])
                         : "memory");
        }
    } else {
        for (int e = base; e < E && e < base + 4; e++) {
            int src, dst;
            if (sI64) {
                const long long* p = (const long long*)eidx;
                src = (int)__ldg(&p[e]); dst = (int)__ldg(&p[(size_t)E + e]);
            } else {
                const int* p = (const int*)eidx;
                src = __ldg(&p[e]); dst = __ldg(&p[E + e]);
            }
            float2 hv = *(const float2*)&g_h1e[2 * src];
            float h0 = fmaf(hv.x, sSc[0], sSh[0]);
            float h1 = fmaf(hv.y, sSc[1], sSh[1]);
            float acc[4];
            combo2(__ldg(&attr[3*e]), __ldg(&attr[3*e+1]), __ldg(&attr[3*e+2]), h0, h1, sW, acc);
            asm volatile("red.global.add.v4.f32 [%0], {%1, %2, %3, %4};"
                         :: "l"(&g.h2[4 * dst]), "f"(acc[0]), "f"(acc[1]), "f"(acc[2]), "f"(acc[3])
                         : "memory");
        }
    }
}

// -------- finish2: mean, BN2 stats + params, PRE-BN grid max/min pool --------
__global__ void __launch_bounds__(256) k_finish2(
        const float* __restrict__ pos,
        const float* __restrict__ gamma2, const float* __restrict__ beta2, int N) {
    __shared__ unsigned smax[64], smin[64];
    int t = threadIdx.x;
    if (t < 64) { smax[t] = ENC_NEG_INF; smin[t] = ENC_MAX; }
    __syncthreads();

    int n = blockIdx.x * 256 + t;
    float m[4] = {0.f, 0.f, 0.f, 0.f};
    if (n < N) {
        float4 h  = *(const float4*)&g.h2[4 * n];
        float inv = g_inv[n];
        m[0] = h.x * inv; m[1] = h.y * inv; m[2] = h.z * inv; m[3] = h.w * inv;
        float2 p = *(const float2*)&pos[2 * n];
        int cx = min(max((int)floorf(p.x * 0.04f), 0), 3);
        int cy = min(max((int)floorf(p.y * 0.04f), 0), 3);
        int cl = 4 * (cx + 4 * cy);
#pragma unroll
        for (int o = 0; o < 4; o++) {
            unsigned e = fenc(m[o]);
            atomicMax(&smax[cl + o], e);
            atomicMin(&smin[cl + o], e);
        }
    }
    float s[8];
#pragma unroll
    for (int o = 0; o < 4; o++) { s[o] = m[o]; s[4 + o] = m[o] * m[o]; }
#pragma unroll
    for (int o = 16; o; o >>= 1)
#pragma unroll
        for (int k = 0; k < 8; k++) s[k] += __shfl_down_sync(~0u, s[k], o);
    if ((t & 31) == 0) {
#pragma unroll
        for (int k = 0; k < 8; k++) atomicAdd(&g.stats[4 + k], (double)s[k]);
    }
    __syncthreads();
    if (t < 64) {
        atomicMax(&g_poolmax[t], smax[t]);
        atomicMin(&g_poolmin[t], smin[t]);
    }
    __shared__ int last;
    __syncthreads();
    if (t == 0) {
        __threadfence();
        last = (atomicAdd(&g.done2, 1u) == gridDim.x - 1);
    }
    __syncthreads();
    if (last && t < 4) {
        __threadfence();
        double invN = 1.0 / (double)N;
        double mu   = g.stats[4 + t] * invN;
        double var  = g.stats[8 + t] * invN - mu * mu;
        float  sc   = (float)((double)gamma2[t] / sqrt(var + 1e-5));
        g_scale2[t] = sc;
        g_shift2[t] = beta2[t] - (float)mu * sc;
    }
}

// ------- fc: apply BN2 to pooled extrema (sign-aware), then [1,64]@W.T -------
__global__ void k_fc(const float* __restrict__ fcw, float* __restrict__ out) {
    __shared__ float v[64];
    int t = threadIdx.x;
    if (t < 64) {
        int   o  = t & 3;
        float sc = g_scale2[o], sh = g_shift2[o];
        unsigned enc = (sc >= 0.f) ? g_poolmax[t] : g_poolmin[t];
        float val = fdec(enc);
        v[t] = isfinite(val) ? fmaf(val, sc, sh) : 0.0f;   // empty cell -> 0
    }
    __syncthreads();
    int w = t >> 5, l = t & 31;
    float p = v[l] * fcw[w * 64 + l] + v[l + 32] * fcw[w * 64 + l + 32];
#pragma unroll
    for (int o = 16; o; o >>= 1) p += __shfl_down_sync(~0u, p, o);
    if (l == 0) out[w] = p;
}

// ---------------- host launcher (graph-capturable) ---------------------------
extern "C" void kernel_launch(void* const* d_in, const int* in_sizes, int n_in,
                              void* d_out, int out_size) {
    const float* x      = (const float*)d_in[0];
    const void*  eidx   = d_in[1];
    const float* attr   = (const float*)d_in[2];
    const float* pos    = (const float*)d_in[3];
    const float* W1     = (const float*)d_in[4];
    const float* W2     = (const float*)d_in[5];
    const float* gamma1 = (const float*)d_in[6];
    const float* beta1  = (const float*)d_in[7];
    const float* gamma2 = (const float*)d_in[8];
    const float* beta2  = (const float*)d_in[9];
    const float* fcw    = (const float*)d_in[10];
    float*       out    = (float*)d_out;

    int N = in_sizes[0];        // x is [N,1]
    int E = in_sizes[2] / 3;    // edge_attr is [E,3]

    void* pg;
    cudaGetSymbolAddress(&pg, g);
    cudaMemsetAsync(pg, 0, sizeof(ScratchT));

    int ebl = (E + 1023) / 1024;   // 4 edges/thread
    int nbl = (N + 255) / 256;

    k_prelude<<<1, 128>>>((const unsigned*)eidx, E);
    k_conv1<<<ebl, 256>>>(x, eidx, attr, W1, E);
    k_finish1<<<nbl, 256>>>(gamma1, beta1, N);
    k_conv2<<<ebl, 256>>>(eidx, attr, W2, E);
    k_finish2<<<nbl, 256>>>(pos, gamma2, beta2, N);
    k_fc<<<1, 128>>>(fcw, out);
}

// round 3
// speedup vs baseline: 1.3693x; 1.3693x over previous
#include <cuda_runtime.h>
#include <math.h>
#include <stdint.h>

#define NMAX 262144

// ---------------- scratch (device globals; no allocation allowed) ------------
struct ScratchT {
    float    h1[4 * NMAX];   // conv1 accum: h0, h1, cnt, pad
    float    h2[4 * NMAX];   // conv2 accum: 4 channels
    double   stats[12];      // sum1[2], sumsq1[2], sum2[4], sumsq2[4]
    unsigned done1, done2;   // last-block counters
};
__device__ ScratchT g;
__device__ float    g_h1e[2 * NMAX];   // elu(mean(h1)) packed float2
__device__ float    g_inv[NMAX];       // 1 / max(cnt,1)
__device__ float    g_scale1[2], g_shift1[2];
__device__ float    g_scale2[4], g_shift2[4];
__device__ unsigned g_poolmax[64], g_poolmin[64];  // pre-BN pooled, ordered-uint
__device__ int      g_idx64;

// ordered-uint encoding: unsigned max/min == float max/min
__device__ __forceinline__ unsigned fenc(float f) {
    unsigned u = __float_as_uint(f);
    return (u & 0x80000000u) ? ~u : (u | 0x80000000u);
}
__device__ __forceinline__ float fdec(unsigned u) {
    return (u & 0x80000000u) ? __uint_as_float(u & 0x7FFFFFFFu)
                             : __uint_as_float(~u);
}
#define ENC_NEG_INF 0x007FFFFFu
#define ENC_MAX     0xFFFFFFFFu

// ---------------- prelude: init pool slots + sniff index dtype ---------------
__global__ void k_prelude(const unsigned* __restrict__ eidx_words, int E) {
    int t = threadIdx.x;
    if (t < 64) { g_poolmax[t] = ENC_NEG_INF; g_poolmin[t] = ENC_MAX; }
    if (t == 0) {
        // int64 little-endian with values < 2^31 => every odd word is 0.
        int is64 = 1;
        int nchk = (E < 64) ? E : 64;
        for (int i = 0; i < nchk; i++)
            if (eidx_words[2 * i + 1] != 0u) { is64 = 0; break; }
        g_idx64 = is64;
    }
}

// ---------------- trilinear basis weights (pseudo in [0,1): lo==0) -----------
__device__ __forceinline__ void basis8(float f0, float f1, float f2, float* w) {
    float gr0 = 1.f - f0, gr1 = 1.f - f1, gr2 = 1.f - f2;
    float a00 = gr0 * gr1, a10 = f0 * gr1, a01 = gr0 * f1, a11 = f0 * f1;
    w[0] = a00 * gr2; w[1] = a10 * gr2; w[2] = a01 * gr2; w[3] = a11 * gr2;
    w[4] = a00 * f2;  w[5] = a10 * f2;  w[6] = a01 * f2;  w[7] = a11 * f2;
}

__device__ __forceinline__ void load_edge(const void* eidx, int e, int E, int is64,
                                          int& src, int& dst) {
    if (is64) {
        const long long* p = (const long long*)eidx;
        src = (int)__ldg(&p[e]);
        dst = (int)__ldg(&p[(size_t)E + e]);
    } else {
        const int* p = (const int*)eidx;
        src = __ldg(&p[e]);
        dst = __ldg(&p[E + e]);
    }
}

// ---------------- conv1: x[N,1] x W1 -> red.v4 (h0,h1,cnt,0) -----------------
__global__ void __launch_bounds__(256) k_conv1(
        const float* __restrict__ x, const void* __restrict__ eidx,
        const float* __restrict__ attr, const float* __restrict__ W1, int E) {
    __shared__ float2 sW[8];     // W1[b][0][0..1]
    __shared__ int    sI64;
    int t = threadIdx.x;
    if (t < 8) sW[t] = ((const float2*)W1)[t];
    if (t == 0) sI64 = g_idx64;
    __syncthreads();

    int e = blockIdx.x * 256 + t;
    if (e >= E) return;

    int src, dst;
    load_edge(eidx, e, E, sI64, src, dst);
    float f0 = __ldg(&attr[3 * e]), f1 = __ldg(&attr[3 * e + 1]), f2 = __ldg(&attr[3 * e + 2]);
    float w[8];
    basis8(f0, f1, f2, w);

    float a0 = 0.f, a1 = 0.f;
#pragma unroll
    for (int b = 0; b < 8; b++) {
        float2 W = sW[b];
        a0 = fmaf(w[b], W.x, a0);
        a1 = fmaf(w[b], W.y, a1);
    }
    float xs = __ldg(&x[src]);
    a0 *= xs; a1 *= xs;

    asm volatile("red.global.add.v4.f32 [%0], {%1, %2, %3, %4};"
                 :: "l"(&g.h1[4 * dst]), "f"(a0), "f"(a1), "f"(1.0f), "f"(0.0f)
                 : "memory");
}

// ---------------- finish1: mean -> ELU -> store, BN1 stats + params ----------
__global__ void __launch_bounds__(256) k_finish1(
        const float* __restrict__ gamma1, const float* __restrict__ beta1, int N) {
    int t = threadIdx.x;
    int n = blockIdx.x * 256 + t;
    float a = 0.f, b = 0.f;
    if (n < N) {
        float4 h  = *(const float4*)&g.h1[4 * n];
        float inv = 1.0f / fmaxf(h.z, 1.0f);
        g_inv[n] = inv;
        a = h.x * inv; b = h.y * inv;
        a = (a > 0.f) ? a : expm1f(a);
        b = (b > 0.f) ? b : expm1f(b);
        *(float2*)&g_h1e[2 * n] = make_float2(a, b);
    }
    float s0 = a, s1 = b, s2 = a * a, s3 = b * b;
#pragma unroll
    for (int o = 16; o; o >>= 1) {
        s0 += __shfl_down_sync(~0u, s0, o);
        s1 += __shfl_down_sync(~0u, s1, o);
        s2 += __shfl_down_sync(~0u, s2, o);
        s3 += __shfl_down_sync(~0u, s3, o);
    }
    if ((t & 31) == 0) {
        atomicAdd(&g.stats[0], (double)s0);
        atomicAdd(&g.stats[1], (double)s1);
        atomicAdd(&g.stats[2], (double)s2);
        atomicAdd(&g.stats[3], (double)s3);
    }
    __shared__ int last;
    __syncthreads();
    if (t == 0) {
        __threadfence();
        last = (atomicAdd(&g.done1, 1u) == gridDim.x - 1);
    }
    __syncthreads();
    if (last && t < 2) {
        __threadfence();
        double invN = 1.0 / (double)N;
        double mu   = g.stats[t] * invN;
        double var  = g.stats[2 + t] * invN - mu * mu;
        float  sc   = (float)((double)gamma1[t] / sqrt(var + 1e-5));
        g_scale1[t] = sc;
        g_shift1[t] = beta1[t] - (float)mu * sc;
    }
}

// ---------------- conv2: BN1(h1e)[N,2] x W2 -> red.v4 [N,4] ------------------
// W2 layout [8][2][4]: row (b,i) is a contiguous float4 -> wide uniform LDS.
__global__ void __launch_bounds__(256) k_conv2(
        const void* __restrict__ eidx, const float* __restrict__ attr,
        const float* __restrict__ W2, int E) {
    __shared__ float4 sW[16];     // sW[2b]=W2[b][0][:], sW[2b+1]=W2[b][1][:]
    __shared__ float  sSc[2], sSh[2];
    __shared__ int    sI64;
    int t = threadIdx.x;
    if (t < 16) sW[t] = ((const float4*)W2)[t];
    if (t < 2)  { sSc[t] = g_scale1[t]; sSh[t] = g_shift1[t]; }
    if (t == 0) sI64 = g_idx64;
    __syncthreads();

    int e = blockIdx.x * 256 + t;
    if (e >= E) return;

    int src, dst;
    load_edge(eidx, e, E, sI64, src, dst);
    float f0 = __ldg(&attr[3 * e]), f1 = __ldg(&attr[3 * e + 1]), f2 = __ldg(&attr[3 * e + 2]);
    float w[8];
    basis8(f0, f1, f2, w);

    float2 hv = *(const float2*)&g_h1e[2 * src];   // L2-resident gather
    float h0 = fmaf(hv.x, sSc[0], sSh[0]);         // fused BN1
    float h1 = fmaf(hv.y, sSc[1], sSh[1]);

    float acc0 = 0.f, acc1 = 0.f, acc2 = 0.f, acc3 = 0.f;
#pragma unroll
    for (int b = 0; b < 8; b++) {
        float4 A = sW[2 * b];       // in-channel 0 row
        float4 B = sW[2 * b + 1];   // in-channel 1 row
        float wb = w[b];
        acc0 = fmaf(wb, fmaf(h1, B.x, h0 * A.x), acc0);
        acc1 = fmaf(wb, fmaf(h1, B.y, h0 * A.y), acc1);
        acc2 = fmaf(wb, fmaf(h1, B.z, h0 * A.z), acc2);
        acc3 = fmaf(wb, fmaf(h1, B.w, h0 * A.w), acc3);
    }
    asm volatile("red.global.add.v4.f32 [%0], {%1, %2, %3, %4};"
                 :: "l"(&g.h2[4 * dst]), "f"(acc0), "f"(acc1), "f"(acc2), "f"(acc3)
                 : "memory");
}

// -------- finish2: mean, BN2 stats + params, PRE-BN grid max/min pool --------
__global__ void __launch_bounds__(256) k_finish2(
        const float* __restrict__ pos,
        const float* __restrict__ gamma2, const float* __restrict__ beta2, int N) {
    __shared__ unsigned smax[64], smin[64];
    int t = threadIdx.x;
    if (t < 64) { smax[t] = ENC_NEG_INF; smin[t] = ENC_MAX; }
    __syncthreads();

    int n = blockIdx.x * 256 + t;
    float m[4] = {0.f, 0.f, 0.f, 0.f};
    if (n < N) {
        float4 h  = *(const float4*)&g.h2[4 * n];
        float inv = g_inv[n];
        m[0] = h.x * inv; m[1] = h.y * inv; m[2] = h.z * inv; m[3] = h.w * inv;
        float2 p = *(const float2*)&pos[2 * n];
        int cx = min(max((int)floorf(p.x * 0.04f), 0), 3);
        int cy = min(max((int)floorf(p.y * 0.04f), 0), 3);
        int cl = 4 * (cx + 4 * cy);
#pragma unroll
        for (int o = 0; o < 4; o++) {
            unsigned enc = fenc(m[o]);
            atomicMax(&smax[cl + o], enc);
            atomicMin(&smin[cl + o], enc);
        }
    }
    float s[8];
#pragma unroll
    for (int o = 0; o < 4; o++) { s[o] = m[o]; s[4 + o] = m[o] * m[o]; }
#pragma unroll
    for (int o = 16; o; o >>= 1)
#pragma unroll
        for (int k = 0; k < 8; k++) s[k] += __shfl_down_sync(~0u, s[k], o);
    if ((t & 31) == 0) {
#pragma unroll
        for (int k = 0; k < 8; k++) atomicAdd(&g.stats[4 + k], (double)s[k]);
    }
    __syncthreads();
    if (t < 64) {
        atomicMax(&g_poolmax[t], smax[t]);
        atomicMin(&g_poolmin[t], smin[t]);
    }
    __shared__ int last;
    __syncthreads();
    if (t == 0) {
        __threadfence();
        last = (atomicAdd(&g.done2, 1u) == gridDim.x - 1);
    }
    __syncthreads();
    if (last && t < 4) {
        __threadfence();
        double invN = 1.0 / (double)N;
        double mu   = g.stats[4 + t] * invN;
        double var  = g.stats[8 + t] * invN - mu * mu;
        float  sc   = (float)((double)gamma2[t] / sqrt(var + 1e-5));
        g_scale2[t] = sc;
        g_shift2[t] = beta2[t] - (float)mu * sc;
    }
}

// ------- fc: apply BN2 to pooled extrema (sign-aware), then [1,64]@W.T -------
__global__ void k_fc(const float* __restrict__ fcw, float* __restrict__ out) {
    __shared__ float v[64];
    int t = threadIdx.x;
    if (t < 64) {
        int   o  = t & 3;
        float sc = g_scale2[o], sh = g_shift2[o];
        unsigned enc = (sc >= 0.f) ? g_poolmax[t] : g_poolmin[t];
        float val = fdec(enc);
        v[t] = isfinite(val) ? fmaf(val, sc, sh) : 0.0f;   // empty cell -> 0
    }
    __syncthreads();
    int w = t >> 5, l = t & 31;
    float p = v[l] * fcw[w * 64 + l] + v[l + 32] * fcw[w * 64 + l + 32];
#pragma unroll
    for (int o = 16; o; o >>= 1) p += __shfl_down_sync(~0u, p, o);
    if (l == 0) out[w] = p;
}

// ---------------- host launcher (graph-capturable) ---------------------------
extern "C" void kernel_launch(void* const* d_in, const int* in_sizes, int n_in,
                              void* d_out, int out_size) {
    const float* x      = (const float*)d_in[0];
    const void*  eidx   = d_in[1];
    const float* attr   = (const float*)d_in[2];
    const float* pos    = (const float*)d_in[3];
    const float* W1     = (const float*)d_in[4];
    const float* W2     = (const float*)d_in[5];
    const float* gamma1 = (const float*)d_in[6];
    const float* beta1  = (const float*)d_in[7];
    const float* gamma2 = (const float*)d_in[8];
    const float* beta2  = (const float*)d_in[9];
    const float* fcw    = (const float*)d_in[10];
    float*       out    = (float*)d_out;

    int N = in_sizes[0];        // x is [N,1]
    int E = in_sizes[2] / 3;    // edge_attr is [E,3]

    void* pg;
    cudaGetSymbolAddress(&pg, g);
    cudaMemsetAsync(pg, 0, sizeof(ScratchT));

    int ebl = (E + 255) / 256;
    int nbl = (N + 255) / 256;

    k_prelude<<<1, 128>>>((const unsigned*)eidx, E);
    k_conv1<<<ebl, 256>>>(x, eidx, attr, W1, E);
    k_finish1<<<nbl, 256>>>(gamma1, beta1, N);
    k_conv2<<<ebl, 256>>>(eidx, attr, W2, E);
    k_finish2<<<nbl, 256>>>(pos, gamma2, beta2, N);
    k_fc<<<1, 128>>>(fcw, out);
}